// round 3
// baseline (speedup 1.0000x reference)
#include <cuda_runtime.h>

#define Bn 512
#define Tn 512
#define Kn 64

// Scratch: per-batch sequence lengths (no allocations allowed -> device global)
__device__ int g_seq[Bn];

// ---------------------------------------------------------------------------
// Kernel 1: seq_lens[b] = int( mean_k( sum_t (x[b,t,k] != 0) ) )
// Per-(b,k) sums over T are exact small ints in fp32; mean over K=64 divides
// by a power of two (exact); int cast truncates -> total >> 6 reproduces it.
// ---------------------------------------------------------------------------
__global__ __launch_bounds__(256) void seqlen_kernel(const float* __restrict__ x) {
    __shared__ int red[256];
    const int b = blockIdx.x;
    const float4* xb = (const float4*)(x + (size_t)b * Tn * Kn);
    int c = 0;
    for (int i = threadIdx.x; i < (Tn * Kn) / 4; i += 256) {
        float4 v = xb[i];
        c += (v.x != 0.0f) + (v.y != 0.0f) + (v.z != 0.0f) + (v.w != 0.0f);
    }
    red[threadIdx.x] = c;
    __syncthreads();
    for (int s = 128; s > 0; s >>= 1) {
        if (threadIdx.x < s) red[threadIdx.x] += red[threadIdx.x + s];
        __syncthreads();
    }
    if (threadIdx.x == 0) g_seq[b] = red[0] >> 6;  // floor(total / 64)
}

// ---------------------------------------------------------------------------
// Kernel 2: Viterbi forward + backtrace, one block per batch, thread = to-tag.
// Strict ascending '>' scan reproduces jnp.argmax first-max tie-breaking
// exactly. Backpointers kept in SMEM (uint8) so backtrace never hits gmem.
// ---------------------------------------------------------------------------

// One candidate update: strict > so the FIRST maximum wins (ascending i).
#define VSTEP(av, tc, bb, idx, ii)                      \
    {                                                   \
        float _s = (av) + (tc);                         \
        bool _g = _s > (bb);                            \
        (bb) = _g ? _s : (bb);                          \
        (idx) = _g ? (ii) : (idx);                      \
    }

__global__ __launch_bounds__(Kn) void viterbi_kernel(
    const float* __restrict__ pots,   // [B, T, K]
    const float* __restrict__ trans,  // [K, K]  (from, to)
    float* __restrict__ out)          // [B, T]  (float32 output dtype)
{
    const int b = blockIdx.x;
    const int j = threadIdx.x;  // to-tag

    __shared__ __align__(16) float alpha[2][Kn];
    __shared__ unsigned char bp[(Tn - 1) * Kn];
    __shared__ unsigned char tags[Tn];

    // Transition column for this to-tag, resident in registers.
    float tcol[Kn];
#pragma unroll
    for (int i = 0; i < Kn; i++) tcol[i] = trans[i * Kn + j];

    const float* pb = pots + (size_t)b * Tn * Kn;
    int sl = g_seq[b];
    if (sl > Tn) sl = Tn;

    alpha[0][j] = pb[j];                 // alpha0 = potentials[:,0,:]
    float pnext = pb[Kn + j];            // prefetch t=1 potentials
    __syncthreads();

    int cur = 0;
    for (int t = 1; t < Tn; t++) {
        const float p = pnext;
        const int tn = (t + 1 < Tn) ? (t + 1) : (Tn - 1);
        pnext = pb[tn * Kn + j];         // prefetch next step

        if (t < sl) {
            const float4* a4 = (const float4*)alpha[cur];
            float b0 = -3.402823466e38f, b1 = -3.402823466e38f;
            int i0 = 0, i1 = 32;
#pragma unroll
            for (int q = 0; q < 8; q++) {
                float4 aL = a4[q];       // broadcast LDS.128, conflict-free
                float4 aH = a4[q + 8];
                VSTEP(aL.x, tcol[4 * q + 0], b0, i0, 4 * q + 0);
                VSTEP(aL.y, tcol[4 * q + 1], b0, i0, 4 * q + 1);
                VSTEP(aL.z, tcol[4 * q + 2], b0, i0, 4 * q + 2);
                VSTEP(aL.w, tcol[4 * q + 3], b0, i0, 4 * q + 3);
                VSTEP(aH.x, tcol[32 + 4 * q + 0], b1, i1, 32 + 4 * q + 0);
                VSTEP(aH.y, tcol[32 + 4 * q + 1], b1, i1, 32 + 4 * q + 1);
                VSTEP(aH.z, tcol[32 + 4 * q + 2], b1, i1, 32 + 4 * q + 2);
                VSTEP(aH.w, tcol[32 + 4 * q + 3], b1, i1, 32 + 4 * q + 3);
            }
            // Merge: low-index chain wins ties (strict > from the high chain).
            const bool g = b1 > b0;
            const float best = g ? b1 : b0;
            const int bi = g ? i1 : i0;

            alpha[cur ^ 1][j] = p + best;
            bp[(t - 1) * Kn + j] = (unsigned char)bi;
        } else {
            // Past sequence end: freeze alpha, identity backpointer.
            alpha[cur ^ 1][j] = alpha[cur][j];
            bp[(t - 1) * Kn + j] = (unsigned char)j;
        }
        cur ^= 1;
        __syncthreads();
    }

    // Backtrace (SMEM pointer-chase) by thread 0.
    if (j == 0) {
        float bv = alpha[cur][0];
        int bt = 0;
#pragma unroll 1
        for (int i = 1; i < Kn; i++) {
            float v = alpha[cur][i];
            if (v > bv) { bv = v; bt = i; }   // first max wins
        }
        int tg = bt;
        tags[Tn - 1] = (unsigned char)tg;
#pragma unroll 1
        for (int t = Tn - 2; t >= 0; t--) {
            tg = bp[t * Kn + tg];
            tags[t] = (unsigned char)tg;
        }
    }
    __syncthreads();

    // Coalesced output write — FLOAT32 tag values (small ints exact in fp32).
    float* ob = out + (size_t)b * Tn;
#pragma unroll
    for (int t = j; t < Tn; t += Kn) ob[t] = (float)tags[t];
}

// ---------------------------------------------------------------------------
extern "C" void kernel_launch(void* const* d_in, const int* in_sizes, int n_in,
                              void* d_out, int out_size) {
    // Bind inputs BY SIZE (elements or bytes), falling back to positional.
    const float* inputs = nullptr;
    const float* transitions = nullptr;
    for (int i = 0; i < n_in; i++) {
        if (in_sizes[i] == Kn * Kn || in_sizes[i] == Kn * Kn * 4)
            transitions = (const float*)d_in[i];
        else if (in_sizes[i] == Bn * Tn * Kn || in_sizes[i] == Bn * Tn * Kn * 4)
            inputs = (const float*)d_in[i];
    }
    if (!inputs) inputs = (const float*)d_in[0];
    if (!transitions) transitions = (const float*)d_in[1];

    float* out = (float*)d_out;  // [512, 512] float32 output

    seqlen_kernel<<<Bn, 256>>>(inputs);
    viterbi_kernel<<<Bn, Kn>>>(inputs, transitions, out);
}